// round 11
// baseline (speedup 1.0000x reference)
#include <cuda_runtime.h>
#include <cuda_bf16.h>
#include <math.h>

#define TT 256
#define BB 128
#define EE 256
#define HH 512
#define G4 2048
#define NK 7
#define NCTAS 128

#define SPH 520
#define SPW 520
#define SP2 264

__device__ __nv_bfloat16 g_Gb[134217728];   // [dir][t][gate][cidx64][thr256][4] bf16
__device__ __nv_bfloat16 g_hb[33554432];    // [dir][t][b][k] bf16
__device__ float g_em[229376];
__device__ float g_lossB[BB];
__device__ unsigned g_flag[8];              // [dir*4 + chunk], monotonic (128 per step)

__device__ __forceinline__ float tanh_fast(float x) {
    float y;
    asm("tanh.approx.f32 %0, %1;" : "=f"(y) : "f"(x));
    return y;
}
__device__ __forceinline__ float sigmoid_fast(float x) {
    return 0.5f * tanh_fast(0.5f * x) + 0.5f;
}

__device__ __forceinline__ unsigned smem_u32(const void* p) {
    return (unsigned)__cvta_generic_to_shared(p);
}

__device__ __forceinline__ void ldsm4(unsigned addr, unsigned* r) {
    asm volatile("ldmatrix.sync.aligned.m8n8.x4.shared.b16 {%0,%1,%2,%3}, [%4];"
                 : "=r"(r[0]), "=r"(r[1]), "=r"(r[2]), "=r"(r[3]) : "r"(addr));
}

__device__ __forceinline__ void mma_bf16(float* c, const unsigned* a, unsigned b0, unsigned b1) {
    asm volatile(
        "mma.sync.aligned.m16n8k16.row.col.f32.bf16.bf16.f32 "
        "{%0,%1,%2,%3},{%4,%5,%6,%7},{%8,%9},{%0,%1,%2,%3};"
        : "+f"(c[0]), "+f"(c[1]), "+f"(c[2]), "+f"(c[3])
        : "r"(a[0]), "r"(a[1]), "r"(a[2]), "r"(a[3]), "r"(b0), "r"(b1));
}

__device__ __forceinline__ void cp_async16(unsigned saddr, const void* gaddr) {
    asm volatile("cp.async.cg.shared.global [%0], [%1], 16;" :: "r"(saddr), "l"(gaddr));
}
__device__ __forceinline__ void cp_commit() { asm volatile("cp.async.commit_group;"); }
__device__ __forceinline__ void cp_wait1() { asm volatile("cp.async.wait_group 1;"); }
__device__ __forceinline__ void cp_wait0() { asm volatile("cp.async.wait_group 0;"); }

__device__ __forceinline__ void cvt4_bf16(__nv_bfloat16* d, float4 v) {
    d[0] = __float2bfloat16_rn(v.x);
    d[1] = __float2bfloat16_rn(v.y);
    d[2] = __float2bfloat16_rn(v.z);
    d[3] = __float2bfloat16_rn(v.w);
}

__device__ __forceinline__ unsigned ldsmA_off(int warp, int lane, int stride) {
    int ar = warp * 16 + (lane & 15);
    int ak = (lane >> 4) * 8;
    return (unsigned)((ar * stride + ak) * 2);
}
__device__ __forceinline__ unsigned ldsmB_off(int lane, int stride) {
    int br = ((lane >> 4) << 3) + (lane & 7);
    int bk = ((lane >> 3) & 1) * 8;
    return (unsigned)((br * stride + bk) * 2);
}

__device__ __forceinline__ void wait_flag_ge(const unsigned* fp, unsigned need) {
    if ((threadIdx.x & 31) == 0) {
        unsigned fv = 0;
        do {
            asm volatile("ld.acquire.gpu.u32 %0, [%1];" : "=r"(fv) : "l"(fp) : "memory");
        } while (fv < need);
    }
    __syncwarp();
}

__device__ __forceinline__ void rc_mma_chunk(int ks0, unsigned haddr, unsigned w0,
                                             unsigned w1, float (*acc)[4]) {
#pragma unroll
    for (int kk = 0; kk < 8; kk++) {
        int ks = ks0 + kk;
        unsigned maf[4];
        unsigned mbf[4];
        unsigned mcf[4];
        ldsm4(haddr + ks * 32, maf);
        ldsm4(w0 + ks * 32, mbf);
        ldsm4(w1 + ks * 32, mcf);
        mma_bf16(acc[0], maf, mbf[0], mbf[1]);
        mma_bf16(acc[1], maf, mbf[2], mbf[3]);
        mma_bf16(acc[2], maf, mcf[0], mcf[1]);
        mma_bf16(acc[3], maf, mcf[2], mcf[3]);
    }
}

// =============== kernel 0: reset publish flags ======================================
__global__ void reset_flags_k() {
    if (threadIdx.x < 8) g_flag[threadIdx.x] = 0u;
}

// =============== kernel 1: embedding gather + input GEMM, 8 t per block =============
// writes g_Gb in recurrent fragment layout: plane[(dir,t,gate,cidx)] of 256thr x 4 bf16
__global__ void __launch_bounds__(256, 1) input_gemm(
    const int* __restrict__ inputData, const float* __restrict__ embed,
    const float* __restrict__ WihF, const float* __restrict__ WihB,
    const float* __restrict__ bihF, const float* __restrict__ bhhF,
    const float* __restrict__ bihB, const float* __restrict__ bhhB)
{
    extern __shared__ __align__(16) char ig_smem[];
    __nv_bfloat16* ig_As = (__nv_bfloat16*)ig_smem;                       // 128 x SP2
    __nv_bfloat16* ig_Xs = (__nv_bfloat16*)(ig_smem + 128 * SP2 * 2);     // 128 x SP2
    __nv_bfloat16* ig_Gs = (__nv_bfloat16*)(ig_smem + 2 * 128 * SP2 * 2); // 16 x 1024
    __shared__ int ig_rows[128];

    const int dir  = blockIdx.z;
    const int tblk = blockIdx.y;
    const int j0   = blockIdx.x * 128;
    const int gsel = j0 >> 9;              // gate index (block never straddles)
    const int cbase = (j0 & 511) >> 3;     // first cidx covered
    const float* __restrict__ Wih = dir ? WihB : WihF;
    const float* __restrict__ bih = dir ? bihB : bihF;
    const float* __restrict__ bhh = dir ? bhhB : bhhF;

    const int ig_tid  = threadIdx.x;
    const int ig_warp = ig_tid >> 5;
    const int ig_lane = ig_tid & 31;

    for (int wi = ig_tid; wi < 128 * 64; wi += 256) {
        int wr = wi >> 6;
        int wk = (wi & 63) * 4;
        float4 wv = *(const float4*)(Wih + (size_t)(j0 + wr) * EE + wk);
        cvt4_bf16(ig_As + wr * SP2 + wk, wv);
    }

    const unsigned ig_aaddr = smem_u32(ig_As) + ldsmA_off(ig_warp, ig_lane, SP2);
    const unsigned ig_xaddr = smem_u32(ig_Xs) + ldsmB_off(ig_lane, SP2);

    const int ig_q = ig_lane & 3;
    const int ig_rq = ig_lane >> 2;
    const int ig_j = j0 + ig_warp * 16 + ig_rq;
    const float ig_bias0 = bih[ig_j] + bhh[ig_j];
    const float ig_bias1 = bih[ig_j + 8] + bhh[ig_j + 8];

    for (int tt = 0; tt < 8; tt++) {
        const int t = tblk * 8 + tt;
        if (ig_tid < 128) ig_rows[ig_tid] = inputData[t * BB + ig_tid];
        __syncthreads();

        for (int xi = ig_tid; xi < 128 * 64; xi += 256) {
            int xb = xi >> 6;
            int xk = (xi & 63) * 4;
            float4 xv = *(const float4*)(embed + (size_t)ig_rows[xb] * EE + xk);
            cvt4_bf16(ig_Xs + xb * SP2 + xk, xv);
        }
        __syncthreads();

        float ig_acc[16][4];
#pragma unroll
        for (int ci = 0; ci < 16; ci++) {
#pragma unroll
            for (int cj = 0; cj < 4; cj++) ig_acc[ci][cj] = 0.0f;
        }

#pragma unroll
        for (int ks = 0; ks < 16; ks++) {
            unsigned ig_af[4];
            ldsm4(ig_aaddr + ks * 32, ig_af);
#pragma unroll
            for (int bt = 0; bt < 8; bt++) {
                unsigned ig_xf[4];
                ldsm4(ig_xaddr + bt * (16 * SP2 * 2) + ks * 32, ig_xf);
                mma_bf16(ig_acc[2 * bt], ig_af, ig_xf[0], ig_xf[1]);
                mma_bf16(ig_acc[2 * bt + 1], ig_af, ig_xf[2], ig_xf[3]);
            }
        }

        // stage into recurrent fragment layout:
        // region = warp*2 + (c>>1); thr = (nt>>1)*32 + ((2q+(c&1))<<2) + (rowq>>1)
        // pp = (nt&1)*2 + (rowq&1)
#pragma unroll
        for (int nt = 0; nt < 16; nt++) {
#pragma unroll
            for (int c = 0; c < 4; c++) {
                int sreg = ig_warp * 2 + (c >> 1);
                int sthr = (nt >> 1) * 32 + ((2 * ig_q + (c & 1)) << 2) + (ig_rq >> 1);
                int spp  = (nt & 1) * 2 + (ig_rq & 1);
                float sval = ig_acc[nt][c] + ((c >> 1) ? ig_bias1 : ig_bias0);
                ig_Gs[sreg * 1024 + sthr * 4 + spp] = __float2bfloat16_rn(sval);
            }
        }
        __syncthreads();

        // coalesced copy-out: 16 planes x 1024 bf16 = 32KB contiguous
        {
            const size_t gbase = (((size_t)(dir * TT + t) * 4 + gsel) * 64 + cbase) * 1024;
            const uint4* srcv = (const uint4*)ig_Gs;
            uint4* dstv = (uint4*)(g_Gb + gbase);
#pragma unroll
            for (int i = 0; i < 8; i++) {
                dstv[i * 256 + ig_tid] = srcv[i * 256 + ig_tid];
            }
        }
        __syncthreads();
    }
}

// =============== kernel 2: persistent BiLSTM recurrence (dataflow sync) =============
__global__ void __launch_bounds__(256, 1) recurrent(
    const float* __restrict__ WhhF, const float* __restrict__ WhhB)
{
    extern __shared__ __align__(16) char rc_smem[];
    __nv_bfloat16* rc_hs = (__nv_bfloat16*)rc_smem;
    __nv_bfloat16* rc_ws = (__nv_bfloat16*)(rc_smem + 128 * SPH * 2);

    const int rc_tid  = threadIdx.x;
    const int rc_warp = rc_tid >> 5;
    const int rc_lane = rc_tid & 31;
    const int rc_bid  = blockIdx.x;
    const int dir     = rc_bid >> 6;
    const int cidx    = rc_bid & 63;
    const int hc0     = cidx * 8;
    const int rc_myck = cidx >> 4;
    const float* __restrict__ Whh = dir ? WhhB : WhhF;

    for (int wi = rc_tid; wi < 32 * 512; wi += 256) {
        int wrow = wi >> 9;
        int wk = wi & 511;
        int wj = (wrow >> 3) * HH + hc0 + (wrow & 7);
        rc_ws[wrow * SPW + wk] = __float2bfloat16_rn(Whh[(size_t)wj * HH + wk]);
    }
    __syncthreads();

    const unsigned rc_hbase = smem_u32(rc_hs);
    const unsigned rc_haddr = rc_hbase + ldsmA_off(rc_warp, rc_lane, SPH);
    const unsigned rc_w0 = smem_u32(rc_ws) + ldsmB_off(rc_lane, SPW);
    const unsigned rc_w1 = rc_w0 + 16 * SPW * 2;

    const int rc_q  = rc_lane & 3;
    const int rc_rq = rc_lane >> 2;
    const int rc_bl = rc_warp * 16 + rc_rq;

    float rc_c[4] = {0.f, 0.f, 0.f, 0.f};

    for (int s = 0; s < TT; s++) {
        const int t = dir ? (TT - 1 - s) : s;

        // coalesced prefetch of this thread's 16 gate preactivations (4 planes x 8B)
        float rc_pg[4][4];
#pragma unroll
        for (int gi = 0; gi < 4; gi++) {
            const __nv_bfloat16* gp = g_Gb +
                (((size_t)(dir * TT + t) * 4 + gi) * 64 + cidx) * 1024 + rc_tid * 4;
            uint2 gv = __ldcg((const uint2*)gp);
            __nv_bfloat162 glo = *(__nv_bfloat162*)&gv.x;
            __nv_bfloat162 ghi = *(__nv_bfloat162*)&gv.y;
            rc_pg[gi][0] = __bfloat162float(glo.x);
            rc_pg[gi][1] = __bfloat162float(glo.y);
            rc_pg[gi][2] = __bfloat162float(ghi.x);
            rc_pg[gi][3] = __bfloat162float(ghi.y);
        }

        float rc_acc[4][4];
#pragma unroll
        for (int gi = 0; gi < 4; gi++) {
#pragma unroll
            for (int pi = 0; pi < 4; pi++) rc_acc[gi][pi] = 0.0f;
        }

        if (s > 0) {
            const int tp = dir ? (t + 1) : (t - 1);
            const uint4* rc_src = (const uint4*)(g_hb + (size_t)(dir * TT + tp) * BB * HH);
            const unsigned rc_need = (unsigned)(128 * s);
#pragma unroll
            for (int ck = 0; ck < 4; ck++) {
                wait_flag_ge(&g_flag[dir * 4 + ck], rc_need);
#pragma unroll
                for (int li = 0; li < 8; li++) {
                    int lv = li * 256 + rc_tid;
                    int lrow = lv >> 4;
                    int lu = lv & 15;
                    unsigned lsa = rc_hbase + (unsigned)((lrow * SPH + ck * 128 + lu * 8) * 2);
                    cp_async16(lsa, (const void*)(rc_src + lrow * 64 + ck * 16 + lu));
                }
                cp_commit();
                if (ck > 0) {
                    cp_wait1();
                    __syncthreads();
                    rc_mma_chunk((ck - 1) * 8, rc_haddr, rc_w0, rc_w1, rc_acc);
                }
            }
            cp_wait0();
            __syncthreads();
            rc_mma_chunk(24, rc_haddr, rc_w0, rc_w1, rc_acc);
        }

        float rc_h[4];
#pragma unroll
        for (int pp = 0; pp < 4; pp++) {
            float pgi = rc_pg[0][pp] + rc_acc[0][pp];
            float pgf = rc_pg[1][pp] + rc_acc[1][pp];
            float pgg = rc_pg[2][pp] + rc_acc[2][pp];
            float pgo = rc_pg[3][pp] + rc_acc[3][pp];
            float piv = sigmoid_fast(pgi);
            float pfv = sigmoid_fast(pgf);
            float pgv = tanh_fast(pgg);
            float pov = sigmoid_fast(pgo);
            rc_c[pp] = pfv * rc_c[pp] + piv * pgv;
            rc_h[pp] = pov * tanh_fast(rc_c[pp]);
        }
        __nv_bfloat16* rc_dst = g_hb + ((size_t)(dir * TT + t) * BB + rc_bl) * HH + hc0 + 2 * rc_q;
        *(__nv_bfloat162*)rc_dst = __nv_bfloat162(__float2bfloat16_rn(rc_h[0]), __float2bfloat16_rn(rc_h[1]));
        *(__nv_bfloat162*)(rc_dst + 8 * HH) = __nv_bfloat162(__float2bfloat16_rn(rc_h[2]), __float2bfloat16_rn(rc_h[3]));

        // per-warp publish: warp's stores ordered by syncwarp, released by lane0
        __syncwarp();
        if (rc_lane == 0) {
            unsigned rc_pd;
            asm volatile("atom.add.release.gpu.u32 %0, [%1], 1;"
                         : "=r"(rc_pd) : "l"(&g_flag[dir * 4 + rc_myck]) : "memory");
        }
    }
}

// =============== kernel 3: emissions, warp per (t, b), vectorized ===================
__global__ void __launch_bounds__(128) emissions_k(
    const float* __restrict__ linW, const float* __restrict__ linb)
{
    const int em_t = blockIdx.y;
    const int em_b = blockIdx.x * 4 + (threadIdx.x >> 5);
    const int em_lane = threadIdx.x & 31;

    float em_acc[NK];
#pragma unroll
    for (int kc = 0; kc < NK; kc++) em_acc[kc] = 0.0f;

#pragma unroll
    for (int dd = 0; dd < 2; dd++) {
        const uint4* em_hp = (const uint4*)(g_hb + ((size_t)(dd * TT + em_t) * BB + em_b) * HH);
#pragma unroll
        for (int it = 0; it < 2; it++) {
            int idx = it * 32 + em_lane;         // uint4 index: dims idx*8..idx*8+7
            uint4 hv = em_hp[idx];
            __nv_bfloat162 p0 = *(__nv_bfloat162*)&hv.x;
            __nv_bfloat162 p1 = *(__nv_bfloat162*)&hv.y;
            __nv_bfloat162 p2 = *(__nv_bfloat162*)&hv.z;
            __nv_bfloat162 p3 = *(__nv_bfloat162*)&hv.w;
            float hf[8];
            hf[0] = __bfloat162float(p0.x); hf[1] = __bfloat162float(p0.y);
            hf[2] = __bfloat162float(p1.x); hf[3] = __bfloat162float(p1.y);
            hf[4] = __bfloat162float(p2.x); hf[5] = __bfloat162float(p2.y);
            hf[6] = __bfloat162float(p3.x); hf[7] = __bfloat162float(p3.y);
#pragma unroll
            for (int kc = 0; kc < NK; kc++) {
                const float4* wr = (const float4*)(linW + kc * (2 * HH) + dd * HH + idx * 8);
                float4 w0 = __ldg(wr);
                float4 w1 = __ldg(wr + 1);
                em_acc[kc] += hf[0] * w0.x + hf[1] * w0.y + hf[2] * w0.z + hf[3] * w0.w
                            + hf[4] * w1.x + hf[5] * w1.y + hf[6] * w1.z + hf[7] * w1.w;
            }
        }
    }
#pragma unroll
    for (int kc = 0; kc < NK; kc++) {
#pragma unroll
        for (int o = 16; o; o >>= 1) em_acc[kc] += __shfl_xor_sync(0xffffffffu, em_acc[kc], o);
    }
    if (em_lane == 0) {
#pragma unroll
        for (int kc = 0; kc < NK; kc++) g_em[((size_t)em_t * BB + em_b) * NK + kc] = em_acc[kc] + linb[kc];
    }
}

// =============== kernel 4: CRF score + forward algorithm =============================
__global__ void __launch_bounds__(32) crf_k(
    const int* __restrict__ labels, const float* __restrict__ trans,
    const float* __restrict__ startT, const float* __restrict__ endT)
{
    const int cb = blockIdx.x;
    const int cl = threadIdx.x;

    float csc = 0.0f;
    for (int ct = cl; ct < TT; ct += 32) {
        int clt = labels[cb * TT + ct];
        csc += g_em[((size_t)ct * BB + cb) * NK + clt];
        if (ct < TT - 1) csc += trans[clt * NK + labels[cb * TT + ct + 1]];
    }
#pragma unroll
    for (int o = 16; o; o >>= 1) csc += __shfl_down_sync(0xffffffffu, csc, o);

    const int ck = (cl < NK) ? cl : 0;
    float ctr[NK];
#pragma unroll
    for (int cj = 0; cj < NK; cj++) ctr[cj] = trans[cj * NK + ck];

    float calpha = startT[ck] + g_em[(size_t)cb * NK + ck];
    for (int ct = 1; ct < TT; ct++) {
        float cv[NK];
        float cm = -3.0e38f;
#pragma unroll
        for (int cj = 0; cj < NK; cj++) {
            cv[cj] = __shfl_sync(0xffffffffu, calpha, cj) + ctr[cj];
            cm = fmaxf(cm, cv[cj]);
        }
        float cs = 0.0f;
#pragma unroll
        for (int cj = 0; cj < NK; cj++) cs += __expf(cv[cj] - cm);
        calpha = cm + __logf(cs) + g_em[((size_t)ct * BB + cb) * NK + ck];
    }
    float cav = calpha + endT[ck];
    float cmm = cav;
#pragma unroll
    for (int cj = 0; cj < NK; cj++) cmm = fmaxf(cmm, __shfl_sync(0xffffffffu, cav, cj));
    float ce = (cl < NK) ? __expf(cav - cmm) : 0.0f;
#pragma unroll
    for (int o = 16; o; o >>= 1) ce += __shfl_down_sync(0xffffffffu, ce, o);

    if (cl == 0) {
        float clogZ = cmm + __logf(ce);
        float cscore = csc + startT[labels[cb * TT]] + endT[labels[cb * TT + TT - 1]];
        g_lossB[cb] = cscore - clogZ;
    }
}

// =============== kernel 5: deterministic final reduce ================================
__global__ void __launch_bounds__(128) final_reduce(float* out)
{
    __shared__ float fr_s[128];
    fr_s[threadIdx.x] = g_lossB[threadIdx.x];
    __syncthreads();
    for (int o = 64; o; o >>= 1) {
        if (threadIdx.x < o) fr_s[threadIdx.x] += fr_s[threadIdx.x + o];
        __syncthreads();
    }
    if (threadIdx.x == 0) out[0] = -fr_s[0];
}

// =============== launch ==============================================================
extern "C" void kernel_launch(void* const* d_in, const int* in_sizes, int n_in,
                              void* d_out, int out_size)
{
    const int*   inputData = (const int*)d_in[0];
    const int*   labels    = (const int*)d_in[1];
    const float* embed     = (const float*)d_in[2];
    const float* WihF = (const float*)d_in[3];
    const float* WhhF = (const float*)d_in[4];
    const float* bihF = (const float*)d_in[5];
    const float* bhhF = (const float*)d_in[6];
    const float* WihB = (const float*)d_in[7];
    const float* WhhB = (const float*)d_in[8];
    const float* bihB = (const float*)d_in[9];
    const float* bhhB = (const float*)d_in[10];
    const float* linW = (const float*)d_in[11];
    const float* linb = (const float*)d_in[12];
    const float* trans = (const float*)d_in[13];
    const float* startT = (const float*)d_in[14];
    const float* endT   = (const float*)d_in[15];

    const int ig_smem_bytes = 2 * 128 * SP2 * 2 + 16 * 1024 * 2;
    const int rc_smem_bytes = 128 * SPH * 2 + 32 * SPW * 2;
    cudaFuncSetAttribute(input_gemm, cudaFuncAttributeMaxDynamicSharedMemorySize, ig_smem_bytes);
    cudaFuncSetAttribute(recurrent, cudaFuncAttributeMaxDynamicSharedMemorySize, rc_smem_bytes);

    reset_flags_k<<<1, 32>>>();

    input_gemm<<<dim3(16, 32, 2), 256, ig_smem_bytes>>>(inputData, embed, WihF, WihB, bihF, bhhF, bihB, bhhB);

    recurrent<<<NCTAS, 256, rc_smem_bytes>>>(WhhF, WhhB);

    emissions_k<<<dim3(32, TT), 128>>>(linW, linb);
    crf_k<<<BB, 32>>>(labels, trans, startT, endT);
    final_reduce<<<1, 128>>>((float*)d_out);
}

// round 12
// speedup vs baseline: 1.0707x; 1.0707x over previous
#include <cuda_runtime.h>
#include <cuda_bf16.h>
#include <cuda_fp8.h>
#include <math.h>

#define TT 256
#define BB 128
#define EE 256
#define HH 512
#define G4 2048
#define NK 7
#define NCTAS 128

#define SPB 528   // recurrent fp8 smem row stride (bytes)
#define SP2 264   // input-gemm smem row stride (halves)

__device__ float g_G[134217728];                       // [dir][t][j][b] fp32
__device__ __align__(256) unsigned char g_h8[33554432]; // [dir][t][b][k] e4m3
__device__ __nv_bfloat16 g_hb[33554432];               // [dir][t][b][k] bf16 (emissions)
__device__ float g_em[229376];
__device__ float g_lossB[BB];
__device__ unsigned g_flag[8];                         // [dir*4+chunk], +16 per step

__device__ __forceinline__ float tanh_fast(float x) {
    float y;
    asm("tanh.approx.f32 %0, %1;" : "=f"(y) : "f"(x));
    return y;
}
__device__ __forceinline__ float sigmoid_fast(float x) {
    return 0.5f * tanh_fast(0.5f * x) + 0.5f;
}

__device__ __forceinline__ unsigned smem_u32(const void* p) {
    return (unsigned)__cvta_generic_to_shared(p);
}

__device__ __forceinline__ void ldsm4(unsigned addr, unsigned* r) {
    asm volatile("ldmatrix.sync.aligned.m8n8.x4.shared.b16 {%0,%1,%2,%3}, [%4];"
                 : "=r"(r[0]), "=r"(r[1]), "=r"(r[2]), "=r"(r[3]) : "r"(addr));
}

__device__ __forceinline__ void mma_bf16(float* c, const unsigned* a, unsigned b0, unsigned b1) {
    asm volatile(
        "mma.sync.aligned.m16n8k16.row.col.f32.bf16.bf16.f32 "
        "{%0,%1,%2,%3},{%4,%5,%6,%7},{%8,%9},{%0,%1,%2,%3};"
        : "+f"(c[0]), "+f"(c[1]), "+f"(c[2]), "+f"(c[3])
        : "r"(a[0]), "r"(a[1]), "r"(a[2]), "r"(a[3]), "r"(b0), "r"(b1));
}

__device__ __forceinline__ void mma_fp8(float* c, const unsigned* a, unsigned b0, unsigned b1) {
    asm volatile(
        "mma.sync.aligned.m16n8k32.row.col.f32.e4m3.e4m3.f32 "
        "{%0,%1,%2,%3},{%4,%5,%6,%7},{%8,%9},{%0,%1,%2,%3};"
        : "+f"(c[0]), "+f"(c[1]), "+f"(c[2]), "+f"(c[3])
        : "r"(a[0]), "r"(a[1]), "r"(a[2]), "r"(a[3]), "r"(b0), "r"(b1));
}

__device__ __forceinline__ void cp_async16(unsigned saddr, const void* gaddr) {
    asm volatile("cp.async.cg.shared.global [%0], [%1], 16;" :: "r"(saddr), "l"(gaddr));
}
__device__ __forceinline__ void cp_commit() { asm volatile("cp.async.commit_group;"); }
__device__ __forceinline__ void cp_wait1() { asm volatile("cp.async.wait_group 1;"); }
__device__ __forceinline__ void cp_wait0() { asm volatile("cp.async.wait_group 0;"); }

__device__ __forceinline__ void cvt4_bf16(__nv_bfloat16* d, float4 v) {
    d[0] = __float2bfloat16_rn(v.x);
    d[1] = __float2bfloat16_rn(v.y);
    d[2] = __float2bfloat16_rn(v.z);
    d[3] = __float2bfloat16_rn(v.w);
}

__device__ __forceinline__ unsigned ldsmA_off(int warp, int lane, int stride) {
    int ar = warp * 16 + (lane & 15);
    int ak = (lane >> 4) * 8;
    return (unsigned)((ar * stride + ak) * 2);
}
__device__ __forceinline__ unsigned ldsmB_off(int lane, int stride) {
    int br = ((lane >> 4) << 3) + (lane & 7);
    int bk = ((lane >> 3) & 1) * 8;
    return (unsigned)((br * stride + bk) * 2);
}

__device__ __forceinline__ void wait_flag_ge(const unsigned* fp, unsigned need) {
    if ((threadIdx.x & 31) == 0) {
        unsigned fv = 0;
        do {
            asm volatile("ld.acquire.gpu.u32 %0, [%1];" : "=r"(fv) : "l"(fp) : "memory");
        } while (fv < need);
    }
    __syncwarp();
}

// fp8 mma over one 128-byte k-chunk (4 k32 slices)
__device__ __forceinline__ void rc_mma_chunk(int c, unsigned haddr, unsigned w0,
                                             unsigned w1, float (*acc)[4]) {
#pragma unroll
    for (int kk = 0; kk < 4; kk++) {
        int ks = c * 4 + kk;
        unsigned maf[4];
        unsigned mbf[4];
        unsigned mcf[4];
        ldsm4(haddr + ks * 32, maf);
        ldsm4(w0 + ks * 32, mbf);
        ldsm4(w1 + ks * 32, mcf);
        mma_fp8(acc[0], maf, mbf[0], mbf[1]);
        mma_fp8(acc[1], maf, mbf[2], mbf[3]);
        mma_fp8(acc[2], maf, mcf[0], mcf[1]);
        mma_fp8(acc[3], maf, mcf[2], mcf[3]);
    }
}

// =============== kernel 0: reset publish flags ======================================
__global__ void reset_flags_k() {
    if (threadIdx.x < 8) g_flag[threadIdx.x] = 0u;
}

// =============== kernel 1: embedding gather + input GEMM (bf16 mma) + bias ==========
__global__ void __launch_bounds__(256, 1) input_gemm(
    const int* __restrict__ inputData, const float* __restrict__ embed,
    const float* __restrict__ WihF, const float* __restrict__ WihB,
    const float* __restrict__ bihF, const float* __restrict__ bhhF,
    const float* __restrict__ bihB, const float* __restrict__ bhhB)
{
    extern __shared__ __align__(16) char ig_smem[];
    __nv_bfloat16* ig_As = (__nv_bfloat16*)ig_smem;
    __nv_bfloat16* ig_Xs = (__nv_bfloat16*)(ig_smem + 128 * SP2 * 2);
    __shared__ int ig_rows[128];

    const int dir = blockIdx.z;
    const int t0  = blockIdx.y * 2;
    const int j0  = blockIdx.x * 128;
    const float* __restrict__ Wih = dir ? WihB : WihF;
    const float* __restrict__ bih = dir ? bihB : bihF;
    const float* __restrict__ bhh = dir ? bhhB : bhhF;

    const int ig_tid  = threadIdx.x;
    const int ig_warp = ig_tid >> 5;
    const int ig_lane = ig_tid & 31;

    for (int wi = ig_tid; wi < 128 * 64; wi += 256) {
        int wr = wi >> 6;
        int wk = (wi & 63) * 4;
        float4 wv = *(const float4*)(Wih + (size_t)(j0 + wr) * EE + wk);
        cvt4_bf16(ig_As + wr * SP2 + wk, wv);
    }

    const unsigned ig_aaddr = smem_u32(ig_As) + ldsmA_off(ig_warp, ig_lane, SP2);
    const unsigned ig_xaddr = smem_u32(ig_Xs) + ldsmB_off(ig_lane, SP2);

    const int ig_q = ig_lane & 3;
    const int ig_rq = ig_lane >> 2;
    const int ig_j = j0 + ig_warp * 16 + ig_rq;
    const float ig_bias0 = bih[ig_j] + bhh[ig_j];
    const float ig_bias1 = bih[ig_j + 8] + bhh[ig_j + 8];

    for (int tt = 0; tt < 2; tt++) {
        const int t = t0 + tt;
        if (ig_tid < 128) ig_rows[ig_tid] = inputData[t * BB + ig_tid];
        __syncthreads();

        for (int xi = ig_tid; xi < 128 * 64; xi += 256) {
            int xb = xi >> 6;
            int xk = (xi & 63) * 4;
            float4 xv = *(const float4*)(embed + (size_t)ig_rows[xb] * EE + xk);
            cvt4_bf16(ig_Xs + xb * SP2 + xk, xv);
        }
        __syncthreads();

        float ig_acc[16][4];
#pragma unroll
        for (int ci = 0; ci < 16; ci++) {
#pragma unroll
            for (int cj = 0; cj < 4; cj++) ig_acc[ci][cj] = 0.0f;
        }

#pragma unroll
        for (int ks = 0; ks < 16; ks++) {
            unsigned ig_af[4];
            ldsm4(ig_aaddr + ks * 32, ig_af);
#pragma unroll
            for (int bt = 0; bt < 8; bt++) {
                unsigned ig_xf[4];
                ldsm4(ig_xaddr + bt * (16 * SP2 * 2) + ks * 32, ig_xf);
                mma_bf16(ig_acc[2 * bt], ig_af, ig_xf[0], ig_xf[1]);
                mma_bf16(ig_acc[2 * bt + 1], ig_af, ig_xf[2], ig_xf[3]);
            }
        }

        const size_t ig_base0 = ((size_t)(dir * TT + t) * G4 + ig_j) * BB;
        const size_t ig_base1 = ig_base0 + 8 * BB;
#pragma unroll
        for (int nt = 0; nt < 16; nt++) {
            int ob = nt * 8 + 2 * ig_q;
            *(float2*)(g_G + ig_base0 + ob) = make_float2(ig_acc[nt][0] + ig_bias0, ig_acc[nt][1] + ig_bias0);
            *(float2*)(g_G + ig_base1 + ob) = make_float2(ig_acc[nt][2] + ig_bias1, ig_acc[nt][3] + ig_bias1);
        }
        __syncthreads();
    }
}

// =============== kernel 2: persistent BiLSTM recurrence (fp8 mma, dataflow) =========
__global__ void __launch_bounds__(256, 1) recurrent(
    const float* __restrict__ WhhF, const float* __restrict__ WhhB)
{
    extern __shared__ __align__(16) unsigned char rc_smem[];
    unsigned char* rc_hs = rc_smem;                // 128 x SPB
    unsigned char* rc_ws = rc_smem + 128 * SPB;    // 32 x SPB

    const int rc_tid  = threadIdx.x;
    const int rc_warp = rc_tid >> 5;
    const int rc_lane = rc_tid & 31;
    const int rc_bid  = blockIdx.x;
    const int dir     = rc_bid >> 6;
    const int hc0     = (rc_bid & 63) * 8;
    const int rc_myck = (rc_bid & 63) >> 4;
    const float* __restrict__ Whh = dir ? WhhB : WhhF;

    for (int wi = rc_tid; wi < 32 * 512; wi += 256) {
        int wrow = wi >> 9;
        int wk = wi & 511;
        int wj = (wrow >> 3) * HH + hc0 + (wrow & 7);
        __nv_fp8_e4m3 wv(Whh[(size_t)wj * HH + wk]);
        rc_ws[wrow * SPB + wk] = *(unsigned char*)&wv;
    }
    __syncthreads();

    const unsigned rc_hbase = smem_u32(rc_hs);
    const unsigned rc_haddr = rc_hbase +
        (unsigned)((rc_warp * 16 + (rc_lane & 15)) * SPB + (rc_lane >> 4) * 16);
    const unsigned rc_w0 = smem_u32(rc_ws) +
        (unsigned)(((((rc_lane >> 4) << 3) + (rc_lane & 7)) * SPB) + ((rc_lane >> 3) & 1) * 16);
    const unsigned rc_w1 = rc_w0 + 16 * SPB;

    const int rc_q  = rc_lane & 3;
    const int rc_rq = rc_lane >> 2;
    const int rc_bl = rc_warp * 16 + rc_rq;

    float rc_c[4] = {0.f, 0.f, 0.f, 0.f};

    for (int s = 0; s < TT; s++) {
        const int t = dir ? (TT - 1 - s) : s;

        const float* rc_Gp = g_G + (size_t)(dir * TT + t) * G4 * BB;
        float rc_pg[4][4];
#pragma unroll
        for (int gi = 0; gi < 4; gi++) {
#pragma unroll
            for (int pp = 0; pp < 4; pp++) {
                int qb = rc_bl + (pp >> 1) * 8;
                int qh = 2 * rc_q + (pp & 1);
                rc_pg[gi][pp] = __ldcg(rc_Gp + (size_t)(gi * HH + hc0 + qh) * BB + qb);
            }
        }

        float rc_acc[4][4];
#pragma unroll
        for (int gi = 0; gi < 4; gi++) {
#pragma unroll
            for (int pi = 0; pi < 4; pi++) rc_acc[gi][pi] = 0.0f;
        }

        if (s > 0) {
            const int tp = dir ? (t + 1) : (t - 1);
            const unsigned char* rc_src = g_h8 + (size_t)(dir * TT + tp) * BB * HH;
            const unsigned rc_need = (unsigned)(16 * s);
#pragma unroll
            for (int ck = 0; ck < 4; ck++) {
                wait_flag_ge(&g_flag[dir * 4 + ck], rc_need);
#pragma unroll
                for (int li = 0; li < 4; li++) {
                    int lv = li * 256 + rc_tid;
                    int lrow = lv >> 3;
                    int lu = lv & 7;
                    unsigned lsa = rc_hbase + (unsigned)(lrow * SPB + ck * 128 + lu * 16);
                    cp_async16(lsa, (const void*)(rc_src + lrow * 512 + ck * 128 + lu * 16));
                }
                cp_commit();
                if (ck > 0) {
                    cp_wait1();
                    __syncthreads();
                    rc_mma_chunk(ck - 1, rc_haddr, rc_w0, rc_w1, rc_acc);
                }
            }
            cp_wait0();
            __syncthreads();
            rc_mma_chunk(3, rc_haddr, rc_w0, rc_w1, rc_acc);
        }

        float rc_h[4];
#pragma unroll
        for (int pp = 0; pp < 4; pp++) {
            float pgi = rc_pg[0][pp] + rc_acc[0][pp];
            float pgf = rc_pg[1][pp] + rc_acc[1][pp];
            float pgg = rc_pg[2][pp] + rc_acc[2][pp];
            float pgo = rc_pg[3][pp] + rc_acc[3][pp];
            float piv = sigmoid_fast(pgi);
            float pfv = sigmoid_fast(pgf);
            float pgv = tanh_fast(pgg);
            float pov = sigmoid_fast(pgo);
            rc_c[pp] = pfv * rc_c[pp] + piv * pgv;
            rc_h[pp] = pov * tanh_fast(rc_c[pp]);
        }

        const size_t rc_ho = ((size_t)(dir * TT + t) * BB + rc_bl) * HH + hc0 + 2 * rc_q;
        // bf16 copy for emissions
        __nv_bfloat16* rc_dstb = g_hb + rc_ho;
        *(__nv_bfloat162*)rc_dstb = __nv_bfloat162(__float2bfloat16_rn(rc_h[0]), __float2bfloat16_rn(rc_h[1]));
        *(__nv_bfloat162*)(rc_dstb + 8 * HH) = __nv_bfloat162(__float2bfloat16_rn(rc_h[2]), __float2bfloat16_rn(rc_h[3]));
        // fp8 for the recurrence
        __nv_fp8x2_e4m3 rc_p01(make_float2(rc_h[0], rc_h[1]));
        __nv_fp8x2_e4m3 rc_p23(make_float2(rc_h[2], rc_h[3]));
        *(unsigned short*)(g_h8 + rc_ho) = *(unsigned short*)&rc_p01;
        *(unsigned short*)(g_h8 + rc_ho + 8 * HH) = *(unsigned short*)&rc_p23;

        __syncthreads();
        if (rc_tid == 0) {
            unsigned rc_pd;
            asm volatile("atom.add.release.gpu.u32 %0, [%1], 1;"
                         : "=r"(rc_pd) : "l"(&g_flag[dir * 4 + rc_myck]) : "memory");
        }
    }
}

// =============== kernel 3: emissions, warp per (t, b), vectorized ===================
__global__ void __launch_bounds__(128) emissions_k(
    const float* __restrict__ linW, const float* __restrict__ linb)
{
    const int em_t = blockIdx.y;
    const int em_b = blockIdx.x * 4 + (threadIdx.x >> 5);
    const int em_lane = threadIdx.x & 31;

    float em_acc[NK];
#pragma unroll
    for (int kc = 0; kc < NK; kc++) em_acc[kc] = 0.0f;

#pragma unroll
    for (int dd = 0; dd < 2; dd++) {
        const uint4* em_hp = (const uint4*)(g_hb + ((size_t)(dd * TT + em_t) * BB + em_b) * HH);
#pragma unroll
        for (int it = 0; it < 2; it++) {
            int idx = it * 32 + em_lane;
            uint4 hv = em_hp[idx];
            __nv_bfloat162 p0 = *(__nv_bfloat162*)&hv.x;
            __nv_bfloat162 p1 = *(__nv_bfloat162*)&hv.y;
            __nv_bfloat162 p2 = *(__nv_bfloat162*)&hv.z;
            __nv_bfloat162 p3 = *(__nv_bfloat162*)&hv.w;
            float hf[8];
            hf[0] = __bfloat162float(p0.x); hf[1] = __bfloat162float(p0.y);
            hf[2] = __bfloat162float(p1.x); hf[3] = __bfloat162float(p1.y);
            hf[4] = __bfloat162float(p2.x); hf[5] = __bfloat162float(p2.y);
            hf[6] = __bfloat162float(p3.x); hf[7] = __bfloat162float(p3.y);
#pragma unroll
            for (int kc = 0; kc < NK; kc++) {
                const float4* wr = (const float4*)(linW + kc * (2 * HH) + dd * HH + idx * 8);
                float4 w0 = __ldg(wr);
                float4 w1 = __ldg(wr + 1);
                em_acc[kc] += hf[0] * w0.x + hf[1] * w0.y + hf[2] * w0.z + hf[3] * w0.w
                            + hf[4] * w1.x + hf[5] * w1.y + hf[6] * w1.z + hf[7] * w1.w;
            }
        }
    }
#pragma unroll
    for (int kc = 0; kc < NK; kc++) {
#pragma unroll
        for (int o = 16; o; o >>= 1) em_acc[kc] += __shfl_xor_sync(0xffffffffu, em_acc[kc], o);
    }
    if (em_lane == 0) {
#pragma unroll
        for (int kc = 0; kc < NK; kc++) g_em[((size_t)em_t * BB + em_b) * NK + kc] = em_acc[kc] + linb[kc];
    }
}

// =============== kernel 4: CRF score + forward algorithm =============================
__global__ void __launch_bounds__(32) crf_k(
    const int* __restrict__ labels, const float* __restrict__ trans,
    const float* __restrict__ startT, const float* __restrict__ endT)
{
    const int cb = blockIdx.x;
    const int cl = threadIdx.x;

    float csc = 0.0f;
    for (int ct = cl; ct < TT; ct += 32) {
        int clt = labels[cb * TT + ct];
        csc += g_em[((size_t)ct * BB + cb) * NK + clt];
        if (ct < TT - 1) csc += trans[clt * NK + labels[cb * TT + ct + 1]];
    }
#pragma unroll
    for (int o = 16; o; o >>= 1) csc += __shfl_down_sync(0xffffffffu, csc, o);

    const int ck = (cl < NK) ? cl : 0;
    float ctr[NK];
#pragma unroll
    for (int cj = 0; cj < NK; cj++) ctr[cj] = trans[cj * NK + ck];

    float calpha = startT[ck] + g_em[(size_t)cb * NK + ck];
    for (int ct = 1; ct < TT; ct++) {
        float cv[NK];
        float cm = -3.0e38f;
#pragma unroll
        for (int cj = 0; cj < NK; cj++) {
            cv[cj] = __shfl_sync(0xffffffffu, calpha, cj) + ctr[cj];
            cm = fmaxf(cm, cv[cj]);
        }
        float cs = 0.0f;
#pragma unroll
        for (int cj = 0; cj < NK; cj++) cs += __expf(cv[cj] - cm);
        calpha = cm + __logf(cs) + g_em[((size_t)ct * BB + cb) * NK + ck];
    }
    float cav = calpha + endT[ck];
    float cmm = cav;
#pragma unroll
    for (int cj = 0; cj < NK; cj++) cmm = fmaxf(cmm, __shfl_sync(0xffffffffu, cav, cj));
    float ce = (cl < NK) ? __expf(cav - cmm) : 0.0f;
#pragma unroll
    for (int o = 16; o; o >>= 1) ce += __shfl_down_sync(0xffffffffu, ce, o);

    if (cl == 0) {
        float clogZ = cmm + __logf(ce);
        float cscore = csc + startT[labels[cb * TT]] + endT[labels[cb * TT + TT - 1]];
        g_lossB[cb] = cscore - clogZ;
    }
}

// =============== kernel 5: deterministic final reduce ================================
__global__ void __launch_bounds__(128) final_reduce(float* out)
{
    __shared__ float fr_s[128];
    fr_s[threadIdx.x] = g_lossB[threadIdx.x];
    __syncthreads();
    for (int o = 64; o; o >>= 1) {
        if (threadIdx.x < o) fr_s[threadIdx.x] += fr_s[threadIdx.x + o];
        __syncthreads();
    }
    if (threadIdx.x == 0) out[0] = -fr_s[0];
}

// =============== launch ==============================================================
extern "C" void kernel_launch(void* const* d_in, const int* in_sizes, int n_in,
                              void* d_out, int out_size)
{
    const int*   inputData = (const int*)d_in[0];
    const int*   labels    = (const int*)d_in[1];
    const float* embed     = (const float*)d_in[2];
    const float* WihF = (const float*)d_in[3];
    const float* WhhF = (const float*)d_in[4];
    const float* bihF = (const float*)d_in[5];
    const float* bhhF = (const float*)d_in[6];
    const float* WihB = (const float*)d_in[7];
    const float* WhhB = (const float*)d_in[8];
    const float* bihB = (const float*)d_in[9];
    const float* bhhB = (const float*)d_in[10];
    const float* linW = (const float*)d_in[11];
    const float* linb = (const float*)d_in[12];
    const float* trans = (const float*)d_in[13];
    const float* startT = (const float*)d_in[14];
    const float* endT   = (const float*)d_in[15];

    const int ig_smem_bytes = 2 * 128 * SP2 * 2;
    const int rc_smem_bytes = 128 * SPB + 32 * SPB;
    cudaFuncSetAttribute(input_gemm, cudaFuncAttributeMaxDynamicSharedMemorySize, ig_smem_bytes);
    cudaFuncSetAttribute(recurrent, cudaFuncAttributeMaxDynamicSharedMemorySize, rc_smem_bytes);

    reset_flags_k<<<1, 32>>>();

    input_gemm<<<dim3(16, 128, 2), 256, ig_smem_bytes>>>(inputData, embed, WihF, WihB, bihF, bhhF, bihB, bhhB);

    recurrent<<<NCTAS, 256, rc_smem_bytes>>>(WhhF, WhhB);

    emissions_k<<<dim3(32, TT), 128>>>(linW, linb);
    crf_k<<<BB, 32>>>(labels, trans, startT, endT);
    final_reduce<<<1, 128>>>((float*)d_out);
}

// round 13
// speedup vs baseline: 1.1845x; 1.1063x over previous
#include <cuda_runtime.h>
#include <cuda_bf16.h>
#include <cuda_fp8.h>
#include <math.h>

#define TT 256
#define BB 128
#define EE 256
#define HH 512
#define G4 2048
#define NK 7
#define NCTAS 128

#define SPB 528   // recurrent fp8 smem row stride (bytes)
#define SP2 264   // input-gemm smem row stride (halves)

__device__ __nv_bfloat16 g_G16[134217728];              // [dir][t][j][b] bf16
__device__ __align__(256) unsigned char g_h8[33554432]; // [dir][t][b][k] e4m3
__device__ float g_em[229376];
__device__ float g_lossB[BB];
__device__ unsigned g_flag[8];                          // [dir*4+chunk], +16 per step

__device__ __forceinline__ float tanh_fast(float x) {
    float y;
    asm("tanh.approx.f32 %0, %1;" : "=f"(y) : "f"(x));
    return y;
}
__device__ __forceinline__ float sigmoid_fast(float x) {
    return 0.5f * tanh_fast(0.5f * x) + 0.5f;
}

__device__ __forceinline__ unsigned smem_u32(const void* p) {
    return (unsigned)__cvta_generic_to_shared(p);
}

__device__ __forceinline__ void ldsm4(unsigned addr, unsigned* r) {
    asm volatile("ldmatrix.sync.aligned.m8n8.x4.shared.b16 {%0,%1,%2,%3}, [%4];"
                 : "=r"(r[0]), "=r"(r[1]), "=r"(r[2]), "=r"(r[3]) : "r"(addr));
}

__device__ __forceinline__ void mma_bf16(float* c, const unsigned* a, unsigned b0, unsigned b1) {
    asm volatile(
        "mma.sync.aligned.m16n8k16.row.col.f32.bf16.bf16.f32 "
        "{%0,%1,%2,%3},{%4,%5,%6,%7},{%8,%9},{%0,%1,%2,%3};"
        : "+f"(c[0]), "+f"(c[1]), "+f"(c[2]), "+f"(c[3])
        : "r"(a[0]), "r"(a[1]), "r"(a[2]), "r"(a[3]), "r"(b0), "r"(b1));
}

__device__ __forceinline__ void mma_fp8(float* c, const unsigned* a, unsigned b0, unsigned b1) {
    asm volatile(
        "mma.sync.aligned.m16n8k32.row.col.f32.e4m3.e4m3.f32 "
        "{%0,%1,%2,%3},{%4,%5,%6,%7},{%8,%9},{%0,%1,%2,%3};"
        : "+f"(c[0]), "+f"(c[1]), "+f"(c[2]), "+f"(c[3])
        : "r"(a[0]), "r"(a[1]), "r"(a[2]), "r"(a[3]), "r"(b0), "r"(b1));
}

__device__ __forceinline__ void cp_async16(unsigned saddr, const void* gaddr) {
    asm volatile("cp.async.cg.shared.global [%0], [%1], 16;" :: "r"(saddr), "l"(gaddr));
}
__device__ __forceinline__ void cp_commit() { asm volatile("cp.async.commit_group;"); }
__device__ __forceinline__ void cp_wait3() { asm volatile("cp.async.wait_group 3;"); }
__device__ __forceinline__ void cp_wait2() { asm volatile("cp.async.wait_group 2;"); }
__device__ __forceinline__ void cp_wait1() { asm volatile("cp.async.wait_group 1;"); }
__device__ __forceinline__ void cp_wait0() { asm volatile("cp.async.wait_group 0;"); }

__device__ __forceinline__ void cvt4_bf16(__nv_bfloat16* d, float4 v) {
    d[0] = __float2bfloat16_rn(v.x);
    d[1] = __float2bfloat16_rn(v.y);
    d[2] = __float2bfloat16_rn(v.z);
    d[3] = __float2bfloat16_rn(v.w);
}

__device__ __forceinline__ unsigned ldsmA_off(int warp, int lane, int stride) {
    int ar = warp * 16 + (lane & 15);
    int ak = (lane >> 4) * 8;
    return (unsigned)((ar * stride + ak) * 2);
}
__device__ __forceinline__ unsigned ldsmB_off(int lane, int stride) {
    int br = ((lane >> 4) << 3) + (lane & 7);
    int bk = ((lane >> 3) & 1) * 8;
    return (unsigned)((br * stride + bk) * 2);
}

// fp8 mma over one 128-byte k-chunk (4 k32 slices)
__device__ __forceinline__ void rc_mma_chunk(int c, unsigned haddr, unsigned w0,
                                             unsigned w1, float (*acc)[4]) {
#pragma unroll
    for (int kk = 0; kk < 4; kk++) {
        int ks = c * 4 + kk;
        unsigned maf[4];
        unsigned mbf[4];
        unsigned mcf[4];
        ldsm4(haddr + ks * 32, maf);
        ldsm4(w0 + ks * 32, mbf);
        ldsm4(w1 + ks * 32, mcf);
        mma_fp8(acc[0], maf, mbf[0], mbf[1]);
        mma_fp8(acc[1], maf, mbf[2], mbf[3]);
        mma_fp8(acc[2], maf, mcf[0], mcf[1]);
        mma_fp8(acc[3], maf, mcf[2], mcf[3]);
    }
}

// =============== kernel 0: reset publish flags ======================================
__global__ void reset_flags_k() {
    if (threadIdx.x < 8) g_flag[threadIdx.x] = 0u;
}

// =============== kernel 1: embedding gather + input GEMM (bf16 mma) + bias ==========
__global__ void __launch_bounds__(256, 1) input_gemm(
    const int* __restrict__ inputData, const float* __restrict__ embed,
    const float* __restrict__ WihF, const float* __restrict__ WihB,
    const float* __restrict__ bihF, const float* __restrict__ bhhF,
    const float* __restrict__ bihB, const float* __restrict__ bhhB)
{
    extern __shared__ __align__(16) char ig_smem[];
    __nv_bfloat16* ig_As = (__nv_bfloat16*)ig_smem;
    __nv_bfloat16* ig_Xs = (__nv_bfloat16*)(ig_smem + 128 * SP2 * 2);
    __shared__ int ig_rows[128];

    const int dir = blockIdx.z;
    const int t0  = blockIdx.y * 2;
    const int j0  = blockIdx.x * 128;
    const float* __restrict__ Wih = dir ? WihB : WihF;
    const float* __restrict__ bih = dir ? bihB : bihF;
    const float* __restrict__ bhh = dir ? bhhB : bhhF;

    const int ig_tid  = threadIdx.x;
    const int ig_warp = ig_tid >> 5;
    const int ig_lane = ig_tid & 31;

    for (int wi = ig_tid; wi < 128 * 64; wi += 256) {
        int wr = wi >> 6;
        int wk = (wi & 63) * 4;
        float4 wv = *(const float4*)(Wih + (size_t)(j0 + wr) * EE + wk);
        cvt4_bf16(ig_As + wr * SP2 + wk, wv);
    }

    const unsigned ig_aaddr = smem_u32(ig_As) + ldsmA_off(ig_warp, ig_lane, SP2);
    const unsigned ig_xaddr = smem_u32(ig_Xs) + ldsmB_off(ig_lane, SP2);

    const int ig_q = ig_lane & 3;
    const int ig_rq = ig_lane >> 2;
    const int ig_j = j0 + ig_warp * 16 + ig_rq;
    const float ig_bias0 = bih[ig_j] + bhh[ig_j];
    const float ig_bias1 = bih[ig_j + 8] + bhh[ig_j + 8];

    for (int tt = 0; tt < 2; tt++) {
        const int t = t0 + tt;
        if (ig_tid < 128) ig_rows[ig_tid] = inputData[t * BB + ig_tid];
        __syncthreads();

        for (int xi = ig_tid; xi < 128 * 64; xi += 256) {
            int xb = xi >> 6;
            int xk = (xi & 63) * 4;
            float4 xv = *(const float4*)(embed + (size_t)ig_rows[xb] * EE + xk);
            cvt4_bf16(ig_Xs + xb * SP2 + xk, xv);
        }
        __syncthreads();

        float ig_acc[16][4];
#pragma unroll
        for (int ci = 0; ci < 16; ci++) {
#pragma unroll
            for (int cj = 0; cj < 4; cj++) ig_acc[ci][cj] = 0.0f;
        }

#pragma unroll
        for (int ks = 0; ks < 16; ks++) {
            unsigned ig_af[4];
            ldsm4(ig_aaddr + ks * 32, ig_af);
#pragma unroll
            for (int bt = 0; bt < 8; bt++) {
                unsigned ig_xf[4];
                ldsm4(ig_xaddr + bt * (16 * SP2 * 2) + ks * 32, ig_xf);
                mma_bf16(ig_acc[2 * bt], ig_af, ig_xf[0], ig_xf[1]);
                mma_bf16(ig_acc[2 * bt + 1], ig_af, ig_xf[2], ig_xf[3]);
            }
        }

        const size_t ig_base0 = ((size_t)(dir * TT + t) * G4 + ig_j) * BB;
        const size_t ig_base1 = ig_base0 + 8 * BB;
#pragma unroll
        for (int nt = 0; nt < 16; nt++) {
            int ob = nt * 8 + 2 * ig_q;
            __nv_bfloat162 bv0(__float2bfloat16_rn(ig_acc[nt][0] + ig_bias0),
                               __float2bfloat16_rn(ig_acc[nt][1] + ig_bias0));
            __nv_bfloat162 bv1(__float2bfloat16_rn(ig_acc[nt][2] + ig_bias1),
                               __float2bfloat16_rn(ig_acc[nt][3] + ig_bias1));
            *(__nv_bfloat162*)(g_G16 + ig_base0 + ob) = bv0;
            *(__nv_bfloat162*)(g_G16 + ig_base1 + ob) = bv1;
        }
        __syncthreads();
    }
}

// =============== kernel 2: persistent BiLSTM recurrence (fp8 mma, dataflow) =========
__global__ void __launch_bounds__(256, 1) recurrent(
    const float* __restrict__ WhhF, const float* __restrict__ WhhB)
{
    extern __shared__ __align__(16) unsigned char rc_smem[];
    unsigned char* rc_hs = rc_smem;                // 128 x SPB
    unsigned char* rc_ws = rc_smem + 128 * SPB;    // 32 x SPB

    const int rc_tid  = threadIdx.x;
    const int rc_warp = rc_tid >> 5;
    const int rc_lane = rc_tid & 31;
    const int rc_bid  = blockIdx.x;
    const int dir     = rc_bid >> 6;
    const int hc0     = (rc_bid & 63) * 8;
    const int rc_myck = (rc_bid & 63) >> 4;
    const float* __restrict__ Whh = dir ? WhhB : WhhF;

    for (int wi = rc_tid; wi < 32 * 512; wi += 256) {
        int wrow = wi >> 9;
        int wk = wi & 511;
        int wj = (wrow >> 3) * HH + hc0 + (wrow & 7);
        __nv_fp8_e4m3 wv(Whh[(size_t)wj * HH + wk]);
        rc_ws[wrow * SPB + wk] = *(unsigned char*)&wv;
    }
    __syncthreads();

    const unsigned rc_hbase = smem_u32(rc_hs);
    const unsigned rc_haddr = rc_hbase +
        (unsigned)((rc_warp * 16 + (rc_lane & 15)) * SPB + (rc_lane >> 4) * 16);
    const unsigned rc_w0 = smem_u32(rc_ws) +
        (unsigned)(((((rc_lane >> 4) << 3) + (rc_lane & 7)) * SPB) + ((rc_lane >> 3) & 1) * 16);
    const unsigned rc_w1 = rc_w0 + 16 * SPB;

    const int rc_q  = rc_lane & 3;
    const int rc_rq = rc_lane >> 2;
    const int rc_bl = rc_warp * 16 + rc_rq;

    float rc_c[4] = {0.f, 0.f, 0.f, 0.f};

    for (int s = 0; s < TT; s++) {
        const int t = dir ? (TT - 1 - s) : s;

        // prefetch gate preactivations (bf16, independent of h)
        const __nv_bfloat16* rc_Gp = g_G16 + (size_t)(dir * TT + t) * G4 * BB;
        float rc_pg[4][4];
#pragma unroll
        for (int gi = 0; gi < 4; gi++) {
#pragma unroll
            for (int pp = 0; pp < 4; pp++) {
                int qb = rc_bl + (pp >> 1) * 8;
                int qh = 2 * rc_q + (pp & 1);
                unsigned short gu = __ldcg((const unsigned short*)
                    (rc_Gp + (size_t)(gi * HH + hc0 + qh) * BB + qb));
                rc_pg[gi][pp] = __bfloat162float(*(__nv_bfloat16*)&gu);
            }
        }

        float rc_acc[4][4];
#pragma unroll
        for (int gi = 0; gi < 4; gi++) {
#pragma unroll
            for (int pi = 0; pi < 4; pi++) rc_acc[gi][pi] = 0.0f;
        }

        if (s > 0) {
            const int tp = dir ? (t + 1) : (t - 1);
            const unsigned char* rc_src = g_h8 + (size_t)(dir * TT + tp) * BB * HH;
            const unsigned rc_need = (unsigned)(16 * s);

            // parallel flag polls: warp w (w<4), lane 0 polls chunk w's flag
            if (rc_warp < 4 && rc_lane == 0) {
                const unsigned* fp = &g_flag[dir * 4 + rc_warp];
                unsigned fv = 0;
                do {
                    asm volatile("ld.acquire.gpu.u32 %0, [%1];" : "=r"(fv) : "l"(fp) : "memory");
                } while (fv < rc_need);
            }
            __syncthreads();

            // issue all 4 chunks as 4 commit groups
#pragma unroll
            for (int ck = 0; ck < 4; ck++) {
#pragma unroll
                for (int li = 0; li < 4; li++) {
                    int lv = li * 256 + rc_tid;
                    int lrow = lv >> 3;
                    int lu = lv & 7;
                    unsigned lsa = rc_hbase + (unsigned)(lrow * SPB + ck * 128 + lu * 16);
                    cp_async16(lsa, (const void*)(rc_src + lrow * 512 + ck * 128 + lu * 16));
                }
                cp_commit();
            }
            cp_wait3();
            __syncthreads();
            rc_mma_chunk(0, rc_haddr, rc_w0, rc_w1, rc_acc);
            cp_wait2();
            __syncthreads();
            rc_mma_chunk(1, rc_haddr, rc_w0, rc_w1, rc_acc);
            cp_wait1();
            __syncthreads();
            rc_mma_chunk(2, rc_haddr, rc_w0, rc_w1, rc_acc);
            cp_wait0();
            __syncthreads();
            rc_mma_chunk(3, rc_haddr, rc_w0, rc_w1, rc_acc);
        }

        float rc_h[4];
#pragma unroll
        for (int pp = 0; pp < 4; pp++) {
            float pgi = rc_pg[0][pp] + rc_acc[0][pp];
            float pgf = rc_pg[1][pp] + rc_acc[1][pp];
            float pgg = rc_pg[2][pp] + rc_acc[2][pp];
            float pgo = rc_pg[3][pp] + rc_acc[3][pp];
            float piv = sigmoid_fast(pgi);
            float pfv = sigmoid_fast(pgf);
            float pgv = tanh_fast(pgg);
            float pov = sigmoid_fast(pgo);
            rc_c[pp] = pfv * rc_c[pp] + piv * pgv;
            rc_h[pp] = pov * tanh_fast(rc_c[pp]);
        }

        const size_t rc_ho = ((size_t)(dir * TT + t) * BB + rc_bl) * HH + hc0 + 2 * rc_q;
        __nv_fp8x2_e4m3 rc_p01(make_float2(rc_h[0], rc_h[1]));
        __nv_fp8x2_e4m3 rc_p23(make_float2(rc_h[2], rc_h[3]));
        *(unsigned short*)(g_h8 + rc_ho) = *(unsigned short*)&rc_p01;
        *(unsigned short*)(g_h8 + rc_ho + 8 * HH) = *(unsigned short*)&rc_p23;

        __syncthreads();
        if (rc_tid == 0) {
            unsigned rc_pd;
            asm volatile("atom.add.release.gpu.u32 %0, [%1], 1;"
                         : "=r"(rc_pd) : "l"(&g_flag[dir * 4 + rc_myck]) : "memory");
        }
    }
}

// =============== kernel 3: emissions, warp per (t, b), fp8 h ========================
__global__ void __launch_bounds__(128) emissions_k(
    const float* __restrict__ linW, const float* __restrict__ linb)
{
    const int em_t = blockIdx.y;
    const int em_b = blockIdx.x * 4 + (threadIdx.x >> 5);
    const int em_lane = threadIdx.x & 31;

    float em_acc[NK];
#pragma unroll
    for (int kc = 0; kc < NK; kc++) em_acc[kc] = 0.0f;

#pragma unroll
    for (int dd = 0; dd < 2; dd++) {
        const uint4* em_hp = (const uint4*)(g_h8 + ((size_t)(dd * TT + em_t) * BB + em_b) * HH);
        uint4 hv = em_hp[em_lane];                 // k = lane*16 .. lane*16+15
        unsigned char hb[16];
        *(uint4*)hb = hv;
        float hf[16];
#pragma unroll
        for (int i = 0; i < 16; i++) {
            hf[i] = float(*(__nv_fp8_e4m3*)&hb[i]);
        }
        const int kbase = dd * HH + em_lane * 16;
#pragma unroll
        for (int kc = 0; kc < NK; kc++) {
            const float4* wr = (const float4*)(linW + kc * (2 * HH) + kbase);
            float4 w0 = __ldg(wr);
            float4 w1 = __ldg(wr + 1);
            float4 w2 = __ldg(wr + 2);
            float4 w3 = __ldg(wr + 3);
            em_acc[kc] += hf[0] * w0.x + hf[1] * w0.y + hf[2] * w0.z + hf[3] * w0.w
                        + hf[4] * w1.x + hf[5] * w1.y + hf[6] * w1.z + hf[7] * w1.w
                        + hf[8] * w2.x + hf[9] * w2.y + hf[10] * w2.z + hf[11] * w2.w
                        + hf[12] * w3.x + hf[13] * w3.y + hf[14] * w3.z + hf[15] * w3.w;
        }
    }
#pragma unroll
    for (int kc = 0; kc < NK; kc++) {
#pragma unroll
        for (int o = 16; o; o >>= 1) em_acc[kc] += __shfl_xor_sync(0xffffffffu, em_acc[kc], o);
    }
    if (em_lane == 0) {
#pragma unroll
        for (int kc = 0; kc < NK; kc++) g_em[((size_t)em_t * BB + em_b) * NK + kc] = em_acc[kc] + linb[kc];
    }
}

// =============== kernel 4: CRF score + forward algorithm =============================
__global__ void __launch_bounds__(32) crf_k(
    const int* __restrict__ labels, const float* __restrict__ trans,
    const float* __restrict__ startT, const float* __restrict__ endT)
{
    const int cb = blockIdx.x;
    const int cl = threadIdx.x;

    float csc = 0.0f;
    for (int ct = cl; ct < TT; ct += 32) {
        int clt = labels[cb * TT + ct];
        csc += g_em[((size_t)ct * BB + cb) * NK + clt];
        if (ct < TT - 1) csc += trans[clt * NK + labels[cb * TT + ct + 1]];
    }
#pragma unroll
    for (int o = 16; o; o >>= 1) csc += __shfl_down_sync(0xffffffffu, csc, o);

    const int ck = (cl < NK) ? cl : 0;
    float ctr[NK];
#pragma unroll
    for (int cj = 0; cj < NK; cj++) ctr[cj] = trans[cj * NK + ck];

    float calpha = startT[ck] + g_em[(size_t)cb * NK + ck];
    for (int ct = 1; ct < TT; ct++) {
        float cv[NK];
        float cm = -3.0e38f;
#pragma unroll
        for (int cj = 0; cj < NK; cj++) {
            cv[cj] = __shfl_sync(0xffffffffu, calpha, cj) + ctr[cj];
            cm = fmaxf(cm, cv[cj]);
        }
        float cs = 0.0f;
#pragma unroll
        for (int cj = 0; cj < NK; cj++) cs += __expf(cv[cj] - cm);
        calpha = cm + __logf(cs) + g_em[((size_t)ct * BB + cb) * NK + ck];
    }
    float cav = calpha + endT[ck];
    float cmm = cav;
#pragma unroll
    for (int cj = 0; cj < NK; cj++) cmm = fmaxf(cmm, __shfl_sync(0xffffffffu, cav, cj));
    float ce = (cl < NK) ? __expf(cav - cmm) : 0.0f;
#pragma unroll
    for (int o = 16; o; o >>= 1) ce += __shfl_down_sync(0xffffffffu, ce, o);

    if (cl == 0) {
        float clogZ = cmm + __logf(ce);
        float cscore = csc + startT[labels[cb * TT]] + endT[labels[cb * TT + TT - 1]];
        g_lossB[cb] = cscore - clogZ;
    }
}

// =============== kernel 5: deterministic final reduce ================================
__global__ void __launch_bounds__(128) final_reduce(float* out)
{
    __shared__ float fr_s[128];
    fr_s[threadIdx.x] = g_lossB[threadIdx.x];
    __syncthreads();
    for (int o = 64; o; o >>= 1) {
        if (threadIdx.x < o) fr_s[threadIdx.x] += fr_s[threadIdx.x + o];
        __syncthreads();
    }
    if (threadIdx.x == 0) out[0] = -fr_s[0];
}

// =============== launch ==============================================================
extern "C" void kernel_launch(void* const* d_in, const int* in_sizes, int n_in,
                              void* d_out, int out_size)
{
    const int*   inputData = (const int*)d_in[0];
    const int*   labels    = (const int*)d_in[1];
    const float* embed     = (const float*)d_in[2];
    const float* WihF = (const float*)d_in[3];
    const float* WhhF = (const float*)d_in[4];
    const float* bihF = (const float*)d_in[5];
    const float* bhhF = (const float*)d_in[6];
    const float* WihB = (const float*)d_in[7];
    const float* WhhB = (const float*)d_in[8];
    const float* bihB = (const float*)d_in[9];
    const float* bhhB = (const float*)d_in[10];
    const float* linW = (const float*)d_in[11];
    const float* linb = (const float*)d_in[12];
    const float* trans = (const float*)d_in[13];
    const float* startT = (const float*)d_in[14];
    const float* endT   = (const float*)d_in[15];

    const int ig_smem_bytes = 2 * 128 * SP2 * 2;
    const int rc_smem_bytes = 128 * SPB + 32 * SPB;
    cudaFuncSetAttribute(input_gemm, cudaFuncAttributeMaxDynamicSharedMemorySize, ig_smem_bytes);
    cudaFuncSetAttribute(recurrent, cudaFuncAttributeMaxDynamicSharedMemorySize, rc_smem_bytes);

    reset_flags_k<<<1, 32>>>();

    input_gemm<<<dim3(16, 128, 2), 256, ig_smem_bytes>>>(inputData, embed, WihF, WihB, bihF, bhhF, bihB, bhhB);

    recurrent<<<NCTAS, 256, rc_smem_bytes>>>(WhhF, WhhB);

    emissions_k<<<dim3(32, TT), 128>>>(linW, linb);
    crf_k<<<BB, 32>>>(labels, trans, startT, endT);
    final_reduce<<<1, 128>>>((float*)d_out);
}

// round 14
// speedup vs baseline: 1.9075x; 1.6103x over previous
#include <cuda_runtime.h>
#include <cuda_bf16.h>
#include <cuda_fp8.h>
#include <math.h>

#define TT 256
#define BB 128
#define EE 256
#define HH 512
#define NK 7
#define NCTAS 128

#define SPB 528    // h smem row stride (bytes)
#define SPX 272    // x / Wih smem row stride (bytes)
#define XBUFB 34816
#define OFF_W 67584
#define OFF_X 84480
#define OFF_WX 154112
#define RC_SMEM 162816

__device__ __align__(256) unsigned char g_X8[8388608];   // [t][b][e] fp8 = embed*16
__device__ __align__(256) unsigned char g_h8[33554432];  // [dir][t][b][k] fp8 = h*16
__device__ float g_em[229376];
__device__ float g_lossB[BB];
__device__ unsigned g_flag[8];                           // [dir*4+chunk], +16 per step

__device__ __forceinline__ float tanh_fast(float x) {
    float y;
    asm("tanh.approx.f32 %0, %1;" : "=f"(y) : "f"(x));
    return y;
}
__device__ __forceinline__ float sigmoid_fast(float x) {
    return 0.5f * tanh_fast(0.5f * x) + 0.5f;
}

__device__ __forceinline__ unsigned smem_u32(const void* p) {
    return (unsigned)__cvta_generic_to_shared(p);
}

__device__ __forceinline__ void ldsm4(unsigned addr, unsigned* r) {
    asm volatile("ldmatrix.sync.aligned.m8n8.x4.shared.b16 {%0,%1,%2,%3}, [%4];"
                 : "=r"(r[0]), "=r"(r[1]), "=r"(r[2]), "=r"(r[3]) : "r"(addr));
}

__device__ __forceinline__ void mma_fp8(float* c, const unsigned* a, unsigned b0, unsigned b1) {
    asm volatile(
        "mma.sync.aligned.m16n8k32.row.col.f32.e4m3.e4m3.f32 "
        "{%0,%1,%2,%3},{%4,%5,%6,%7},{%8,%9},{%0,%1,%2,%3};"
        : "+f"(c[0]), "+f"(c[1]), "+f"(c[2]), "+f"(c[3])
        : "r"(a[0]), "r"(a[1]), "r"(a[2]), "r"(a[3]), "r"(b0), "r"(b1));
}

__device__ __forceinline__ void cp_async16(unsigned saddr, const void* gaddr) {
    asm volatile("cp.async.cg.shared.global [%0], [%1], 16;" :: "r"(saddr), "l"(gaddr));
}
__device__ __forceinline__ void cp_commit() { asm volatile("cp.async.commit_group;"); }
__device__ __forceinline__ void cp_wait3() { asm volatile("cp.async.wait_group 3;"); }
__device__ __forceinline__ void cp_wait2() { asm volatile("cp.async.wait_group 2;"); }
__device__ __forceinline__ void cp_wait1() { asm volatile("cp.async.wait_group 1;"); }
__device__ __forceinline__ void cp_wait0() { asm volatile("cp.async.wait_group 0;"); }

__device__ __forceinline__ float2 fp8x2_to_float2_div16(unsigned short v) {
    unsigned hp;
    asm("cvt.rn.f16x2.e4m3x2 %0, %1;" : "=r"(hp) : "h"(v));
    __half2 hh = *(__half2*)&hp;
    float2 f = __half22float2(hh);
    f.x *= 0.0625f;
    f.y *= 0.0625f;
    return f;
}

// =============== kernel 0: reset publish flags ======================================
__global__ void reset_flags_k() {
    if (threadIdx.x < 8) g_flag[threadIdx.x] = 0u;
}

// =============== kernel 1: embed gather -> fp8 X (x16) ==============================
__global__ void __launch_bounds__(256) embed_gather(
    const int* __restrict__ inputData, const float* __restrict__ embed)
{
    const int eg_t = blockIdx.x;
    const int eg_b = blockIdx.y * 8 + (threadIdx.x >> 5);
    const int eg_lane = threadIdx.x & 31;
    const int eg_row = inputData[eg_t * BB + eg_b];
    const float4* eg_src = (const float4*)(embed + (size_t)eg_row * EE) + eg_lane * 2;
    float4 v0 = __ldg(eg_src);
    float4 v1 = __ldg(eg_src + 1);
    v0.x *= 16.f; v0.y *= 16.f; v0.z *= 16.f; v0.w *= 16.f;
    v1.x *= 16.f; v1.y *= 16.f; v1.z *= 16.f; v1.w *= 16.f;
    __nv_fp8x4_e4m3 p0(v0);
    __nv_fp8x4_e4m3 p1(v1);
    uint2 ov;
    ov.x = *(unsigned*)&p0;
    ov.y = *(unsigned*)&p1;
    *(uint2*)(g_X8 + ((size_t)eg_t * BB + eg_b) * EE + eg_lane * 8) = ov;
}

// =============== kernel 2: persistent fused BiLSTM (fp8 mma, dataflow) ==============
__global__ void __launch_bounds__(256, 1) recurrent(
    const float* __restrict__ WhhF, const float* __restrict__ WhhB,
    const float* __restrict__ WihF, const float* __restrict__ WihB,
    const float* __restrict__ bihF, const float* __restrict__ bhhF,
    const float* __restrict__ bihB, const float* __restrict__ bhhB)
{
    extern __shared__ __align__(16) unsigned char rc_smem[];

    const int rc_tid  = threadIdx.x;
    const int rc_warp = rc_tid >> 5;
    const int rc_lane = rc_tid & 31;
    const int rc_bid  = blockIdx.x;
    const int dir     = rc_bid >> 6;
    const int hc0     = (rc_bid & 63) * 8;
    const int rc_myck = (rc_bid & 63) >> 4;
    const float* __restrict__ Whh = dir ? WhhB : WhhF;
    const float* __restrict__ Wih = dir ? WihB : WihF;
    const float* __restrict__ bih = dir ? bihB : bihF;
    const float* __restrict__ bhh = dir ? bhhB : bhhF;

    // one-time weight loads (x64 into fp8 sweet spot)
    for (int wi = rc_tid; wi < 32 * 512; wi += 256) {
        int wrow = wi >> 9;
        int wk = wi & 511;
        int wj = (wrow >> 3) * HH + hc0 + (wrow & 7);
        __nv_fp8_e4m3 wv(Whh[(size_t)wj * HH + wk] * 64.0f);
        rc_smem[OFF_W + wrow * SPB + wk] = *(unsigned char*)&wv;
    }
    for (int wi = rc_tid; wi < 32 * 256; wi += 256) {
        int wrow = wi >> 8;
        int wk = wi & 255;
        int wj = (wrow >> 3) * HH + hc0 + (wrow & 7);
        __nv_fp8_e4m3 wv(Wih[(size_t)wj * EE + wk] * 64.0f);
        rc_smem[OFF_WX + wrow * SPX + wk] = *(unsigned char*)&wv;
    }

    const int rc_q  = rc_lane & 3;
    const int rc_rq = rc_lane >> 2;
    const int rc_bl = rc_warp * 16 + rc_rq;

    // bias registers: bias_r[gate][hcl&1] with hcl = 2q + (p&1)
    float bias_r[4][2];
#pragma unroll
    for (int gi = 0; gi < 4; gi++) {
#pragma unroll
        for (int hb = 0; hb < 2; hb++) {
            int bj = gi * HH + hc0 + 2 * rc_q + hb;
            bias_r[gi][hb] = bih[bj] + bhh[bj];
        }
    }

    const unsigned rc_base = smem_u32(rc_smem);
    const unsigned rc_ha = rc_base + (unsigned)((rc_warp * 16 + (rc_lane & 15)) * SPB + (rc_lane >> 4) * 16);
    const unsigned rc_wh0 = rc_base + OFF_W +
        (unsigned)(((((rc_lane >> 4) << 3) + (rc_lane & 7)) * SPB) + ((rc_lane >> 3) & 1) * 16);
    const unsigned rc_wh1 = rc_wh0 + 16 * SPB;
    const unsigned rc_xa0 = rc_base + OFF_X +
        (unsigned)((rc_warp * 16 + (rc_lane & 15)) * SPX + (rc_lane >> 4) * 16);
    const unsigned rc_wx0 = rc_base + OFF_WX +
        (unsigned)(((((rc_lane >> 4) << 3) + (rc_lane & 7)) * SPX) + ((rc_lane >> 3) & 1) * 16);
    const unsigned rc_wx1 = rc_wx0 + 16 * SPX;

    // preload X[t0] into buffer 0
    {
        const int t0 = dir ? (TT - 1) : 0;
        const unsigned char* xsrc = g_X8 + (size_t)t0 * BB * EE;
#pragma unroll
        for (int li = 0; li < 8; li++) {
            int lv = li * 256 + rc_tid;
            int lrow = lv >> 4;
            int lu = lv & 15;
            cp_async16(rc_base + OFF_X + (unsigned)(lrow * SPX + lu * 16),
                       (const void*)(xsrc + lrow * EE + lu * 16));
        }
        cp_commit();
        cp_wait0();
    }
    __syncthreads();

    float rc_c[4] = {0.f, 0.f, 0.f, 0.f};

    for (int s = 0; s < TT; s++) {
        const int t = dir ? (TT - 1 - s) : s;
        const int cur = s & 1;
        const unsigned xcur = rc_xa0 + (unsigned)(cur * XBUFB);

        // prefetch next step's X (independent of everything)
        if (s + 1 < TT) {
            const int tn = dir ? (t - 1) : (t + 1);
            const unsigned char* xsrc = g_X8 + (size_t)tn * BB * EE;
            const unsigned xdst = rc_base + OFF_X + (unsigned)((cur ^ 1) * XBUFB);
#pragma unroll
            for (int li = 0; li < 8; li++) {
                int lv = li * 256 + rc_tid;
                int lrow = lv >> 4;
                int lu = lv & 15;
                cp_async16(xdst + (unsigned)(lrow * SPX + lu * 16),
                           (const void*)(xsrc + lrow * EE + lu * 16));
            }
            cp_commit();
        }

        float rc_acc[4][4];
#pragma unroll
        for (int gi = 0; gi < 4; gi++) {
#pragma unroll
            for (int pi = 0; pi < 4; pi++) rc_acc[gi][pi] = 0.0f;
        }

        if (s > 0) {
            const int tp = dir ? (t + 1) : (t - 1);
            const unsigned char* rc_src = g_h8 + (size_t)(dir * TT + tp) * BB * HH;
            const unsigned rc_need = (unsigned)(16 * s);

            // warps 4-7 overlap X-mma with the polls of warps 0-3
            if (rc_warp >= 4) {
#pragma unroll
                for (int ks = 0; ks < 8; ks++) {
                    unsigned xaf[4];
                    unsigned xbf[4];
                    unsigned xcf[4];
                    ldsm4(xcur + ks * 32, xaf);
                    ldsm4(rc_wx0 + ks * 32, xbf);
                    ldsm4(rc_wx1 + ks * 32, xcf);
                    mma_fp8(rc_acc[0], xaf, xbf[0], xbf[1]);
                    mma_fp8(rc_acc[1], xaf, xbf[2], xbf[3]);
                    mma_fp8(rc_acc[2], xaf, xcf[0], xcf[1]);
                    mma_fp8(rc_acc[3], xaf, xcf[2], xcf[3]);
                }
            } else if (rc_lane == 0) {
                const unsigned* fp = &g_flag[dir * 4 + rc_warp];
                unsigned fv = 0;
                do {
                    asm volatile("ld.acquire.gpu.u32 %0, [%1];" : "=r"(fv) : "l"(fp) : "memory");
                } while (fv < rc_need);
            }
            __syncthreads();

            // issue 4 h-chunk groups
#pragma unroll
            for (int ck = 0; ck < 4; ck++) {
#pragma unroll
                for (int li = 0; li < 4; li++) {
                    int lv = li * 256 + rc_tid;
                    int lrow = lv >> 3;
                    int lu = lv & 7;
                    cp_async16(rc_base + (unsigned)(lrow * SPB + ck * 128 + lu * 16),
                               (const void*)(rc_src + lrow * 512 + ck * 128 + lu * 16));
                }
                cp_commit();
            }

            // warps 0-3 do their X-mma while h chunks are in flight
            if (rc_warp < 4) {
#pragma unroll
                for (int ks = 0; ks < 8; ks++) {
                    unsigned xaf[4];
                    unsigned xbf[4];
                    unsigned xcf[4];
                    ldsm4(xcur + ks * 32, xaf);
                    ldsm4(rc_wx0 + ks * 32, xbf);
                    ldsm4(rc_wx1 + ks * 32, xcf);
                    mma_fp8(rc_acc[0], xaf, xbf[0], xbf[1]);
                    mma_fp8(rc_acc[1], xaf, xbf[2], xbf[3]);
                    mma_fp8(rc_acc[2], xaf, xcf[0], xcf[1]);
                    mma_fp8(rc_acc[3], xaf, xcf[2], xcf[3]);
                }
            }

            cp_wait3();
            __syncthreads();
#pragma unroll
            for (int kk = 0; kk < 4; kk++) {
                unsigned haf[4];
                unsigned hbf[4];
                unsigned hcf[4];
                ldsm4(rc_ha + kk * 32, haf);
                ldsm4(rc_wh0 + kk * 32, hbf);
                ldsm4(rc_wh1 + kk * 32, hcf);
                mma_fp8(rc_acc[0], haf, hbf[0], hbf[1]);
                mma_fp8(rc_acc[1], haf, hbf[2], hbf[3]);
                mma_fp8(rc_acc[2], haf, hcf[0], hcf[1]);
                mma_fp8(rc_acc[3], haf, hcf[2], hcf[3]);
            }
            cp_wait2();
            __syncthreads();
#pragma unroll
            for (int kk = 4; kk < 8; kk++) {
                unsigned haf[4];
                unsigned hbf[4];
                unsigned hcf[4];
                ldsm4(rc_ha + kk * 32, haf);
                ldsm4(rc_wh0 + kk * 32, hbf);
                ldsm4(rc_wh1 + kk * 32, hcf);
                mma_fp8(rc_acc[0], haf, hbf[0], hbf[1]);
                mma_fp8(rc_acc[1], haf, hbf[2], hbf[3]);
                mma_fp8(rc_acc[2], haf, hcf[0], hcf[1]);
                mma_fp8(rc_acc[3], haf, hcf[2], hcf[3]);
            }
            cp_wait1();
            __syncthreads();
#pragma unroll
            for (int kk = 8; kk < 12; kk++) {
                unsigned haf[4];
                unsigned hbf[4];
                unsigned hcf[4];
                ldsm4(rc_ha + kk * 32, haf);
                ldsm4(rc_wh0 + kk * 32, hbf);
                ldsm4(rc_wh1 + kk * 32, hcf);
                mma_fp8(rc_acc[0], haf, hbf[0], hbf[1]);
                mma_fp8(rc_acc[1], haf, hbf[2], hbf[3]);
                mma_fp8(rc_acc[2], haf, hcf[0], hcf[1]);
                mma_fp8(rc_acc[3], haf, hcf[2], hcf[3]);
            }
            cp_wait0();
            __syncthreads();
#pragma unroll
            for (int kk = 12; kk < 16; kk++) {
                unsigned haf[4];
                unsigned hbf[4];
                unsigned hcf[4];
                ldsm4(rc_ha + kk * 32, haf);
                ldsm4(rc_wh0 + kk * 32, hbf);
                ldsm4(rc_wh1 + kk * 32, hcf);
                mma_fp8(rc_acc[0], haf, hbf[0], hbf[1]);
                mma_fp8(rc_acc[1], haf, hbf[2], hbf[3]);
                mma_fp8(rc_acc[2], haf, hcf[0], hcf[1]);
                mma_fp8(rc_acc[3], haf, hcf[2], hcf[3]);
            }
        } else {
#pragma unroll
            for (int ks = 0; ks < 8; ks++) {
                unsigned xaf[4];
                unsigned xbf[4];
                unsigned xcf[4];
                ldsm4(xcur + ks * 32, xaf);
                ldsm4(rc_wx0 + ks * 32, xbf);
                ldsm4(rc_wx1 + ks * 32, xcf);
                mma_fp8(rc_acc[0], xaf, xbf[0], xbf[1]);
                mma_fp8(rc_acc[1], xaf, xbf[2], xbf[3]);
                mma_fp8(rc_acc[2], xaf, xcf[0], xcf[1]);
                mma_fp8(rc_acc[3], xaf, xcf[2], xcf[3]);
            }
            cp_wait0();
            __syncthreads();
        }

        // epilogue: gates = acc/1024 + bias  (X*16 * W*64, h*16 * W*64)
        float rc_h[4];
#pragma unroll
        for (int pp = 0; pp < 4; pp++) {
            const float ksc = 0.0009765625f;
            float pgi = rc_acc[0][pp] * ksc + bias_r[0][pp & 1];
            float pgf = rc_acc[1][pp] * ksc + bias_r[1][pp & 1];
            float pgg = rc_acc[2][pp] * ksc + bias_r[2][pp & 1];
            float pgo = rc_acc[3][pp] * ksc + bias_r[3][pp & 1];
            float piv = sigmoid_fast(pgi);
            float pfv = sigmoid_fast(pgf);
            float pgv = tanh_fast(pgg);
            float pov = sigmoid_fast(pgo);
            rc_c[pp] = pfv * rc_c[pp] + piv * pgv;
            rc_h[pp] = pov * tanh_fast(rc_c[pp]);
        }

        const size_t rc_ho = ((size_t)(dir * TT + t) * BB + rc_bl) * HH + hc0 + 2 * rc_q;
        __nv_fp8x2_e4m3 rc_p01(make_float2(rc_h[0] * 16.0f, rc_h[1] * 16.0f));
        __nv_fp8x2_e4m3 rc_p23(make_float2(rc_h[2] * 16.0f, rc_h[3] * 16.0f));
        *(unsigned short*)(g_h8 + rc_ho) = *(unsigned short*)&rc_p01;
        *(unsigned short*)(g_h8 + rc_ho + 8 * HH) = *(unsigned short*)&rc_p23;

        __syncthreads();
        if (rc_tid == 0) {
            asm volatile("red.release.gpu.global.add.u32 [%0], %1;"
                         :: "l"(&g_flag[dir * 4 + rc_myck]), "r"(1u) : "memory");
        }
    }
}

// =============== kernel 3: emissions, warp per (t, b), fp8 h (x16) ==================
__global__ void __launch_bounds__(128) emissions_k(
    const float* __restrict__ linW, const float* __restrict__ linb)
{
    const int em_t = blockIdx.y;
    const int em_b = blockIdx.x * 4 + (threadIdx.x >> 5);
    const int em_lane = threadIdx.x & 31;

    float em_acc[NK];
#pragma unroll
    for (int kc = 0; kc < NK; kc++) em_acc[kc] = 0.0f;

#pragma unroll
    for (int dd = 0; dd < 2; dd++) {
        const uint4* em_hp = (const uint4*)(g_h8 + ((size_t)(dd * TT + em_t) * BB + em_b) * HH);
        uint4 hv = em_hp[em_lane];                 // k = lane*16 .. lane*16+15
        unsigned short hs[8];
        *(uint4*)hs = hv;
        float hf[16];
#pragma unroll
        for (int i = 0; i < 8; i++) {
            float2 fp = fp8x2_to_float2_div16(hs[i]);
            hf[2 * i] = fp.x;
            hf[2 * i + 1] = fp.y;
        }
        const int kbase = dd * HH + em_lane * 16;
#pragma unroll
        for (int kc = 0; kc < NK; kc++) {
            const float4* wr = (const float4*)(linW + kc * (2 * HH) + kbase);
            float4 w0 = __ldg(wr);
            float4 w1 = __ldg(wr + 1);
            float4 w2 = __ldg(wr + 2);
            float4 w3 = __ldg(wr + 3);
            em_acc[kc] += hf[0] * w0.x + hf[1] * w0.y + hf[2] * w0.z + hf[3] * w0.w
                        + hf[4] * w1.x + hf[5] * w1.y + hf[6] * w1.z + hf[7] * w1.w
                        + hf[8] * w2.x + hf[9] * w2.y + hf[10] * w2.z + hf[11] * w2.w
                        + hf[12] * w3.x + hf[13] * w3.y + hf[14] * w3.z + hf[15] * w3.w;
        }
    }
#pragma unroll
    for (int kc = 0; kc < NK; kc++) {
#pragma unroll
        for (int o = 16; o; o >>= 1) em_acc[kc] += __shfl_xor_sync(0xffffffffu, em_acc[kc], o);
    }
    if (em_lane == 0) {
#pragma unroll
        for (int kc = 0; kc < NK; kc++) g_em[((size_t)em_t * BB + em_b) * NK + kc] = em_acc[kc] + linb[kc];
    }
}

// =============== kernel 4: CRF score + forward algorithm =============================
__global__ void __launch_bounds__(32) crf_k(
    const int* __restrict__ labels, const float* __restrict__ trans,
    const float* __restrict__ startT, const float* __restrict__ endT)
{
    const int cb = blockIdx.x;
    const int cl = threadIdx.x;

    float csc = 0.0f;
    for (int ct = cl; ct < TT; ct += 32) {
        int clt = labels[cb * TT + ct];
        csc += g_em[((size_t)ct * BB + cb) * NK + clt];
        if (ct < TT - 1) csc += trans[clt * NK + labels[cb * TT + ct + 1]];
    }
#pragma unroll
    for (int o = 16; o; o >>= 1) csc += __shfl_down_sync(0xffffffffu, csc, o);

    const int ck = (cl < NK) ? cl : 0;
    float ctr[NK];
#pragma unroll
    for (int cj = 0; cj < NK; cj++) ctr[cj] = trans[cj * NK + ck];

    float calpha = startT[ck] + g_em[(size_t)cb * NK + ck];
    for (int ct = 1; ct < TT; ct++) {
        float cv[NK];
        float cm = -3.0e38f;
#pragma unroll
        for (int cj = 0; cj < NK; cj++) {
            cv[cj] = __shfl_sync(0xffffffffu, calpha, cj) + ctr[cj];
            cm = fmaxf(cm, cv[cj]);
        }
        float cs = 0.0f;
#pragma unroll
        for (int cj = 0; cj < NK; cj++) cs += __expf(cv[cj] - cm);
        calpha = cm + __logf(cs) + g_em[((size_t)ct * BB + cb) * NK + ck];
    }
    float cav = calpha + endT[ck];
    float cmm = cav;
#pragma unroll
    for (int cj = 0; cj < NK; cj++) cmm = fmaxf(cmm, __shfl_sync(0xffffffffu, cav, cj));
    float ce = (cl < NK) ? __expf(cav - cmm) : 0.0f;
#pragma unroll
    for (int o = 16; o; o >>= 1) ce += __shfl_down_sync(0xffffffffu, ce, o);

    if (cl == 0) {
        float clogZ = cmm + __logf(ce);
        float cscore = csc + startT[labels[cb * TT]] + endT[labels[cb * TT + TT - 1]];
        g_lossB[cb] = cscore - clogZ;
    }
}

// =============== kernel 5: deterministic final reduce ================================
__global__ void __launch_bounds__(128) final_reduce(float* out)
{
    __shared__ float fr_s[128];
    fr_s[threadIdx.x] = g_lossB[threadIdx.x];
    __syncthreads();
    for (int o = 64; o; o >>= 1) {
        if (threadIdx.x < o) fr_s[threadIdx.x] += fr_s[threadIdx.x + o];
        __syncthreads();
    }
    if (threadIdx.x == 0) out[0] = -fr_s[0];
}

// =============== launch ==============================================================
extern "C" void kernel_launch(void* const* d_in, const int* in_sizes, int n_in,
                              void* d_out, int out_size)
{
    const int*   inputData = (const int*)d_in[0];
    const int*   labels    = (const int*)d_in[1];
    const float* embed     = (const float*)d_in[2];
    const float* WihF = (const float*)d_in[3];
    const float* WhhF = (const float*)d_in[4];
    const float* bihF = (const float*)d_in[5];
    const float* bhhF = (const float*)d_in[6];
    const float* WihB = (const float*)d_in[7];
    const float* WhhB = (const float*)d_in[8];
    const float* bihB = (const float*)d_in[9];
    const float* bhhB = (const float*)d_in[10];
    const float* linW = (const float*)d_in[11];
    const float* linb = (const float*)d_in[12];
    const float* trans = (const float*)d_in[13];
    const float* startT = (const float*)d_in[14];
    const float* endT   = (const float*)d_in[15];

    cudaFuncSetAttribute(recurrent, cudaFuncAttributeMaxDynamicSharedMemorySize, RC_SMEM);

    reset_flags_k<<<1, 32>>>();
    embed_gather<<<dim3(TT, 16), 256>>>(inputData, embed);

    recurrent<<<NCTAS, 256, RC_SMEM>>>(WhhF, WhhB, WihF, WihB, bihF, bhhF, bihB, bhhB);

    emissions_k<<<dim3(32, TT), 128>>>(linW, linb);
    crf_k<<<BB, 32>>>(labels, trans, startT, endT);
    final_reduce<<<1, 128>>>((float*)d_out);
}